// round 11
// baseline (speedup 1.0000x reference)
#include <cuda_runtime.h>
#include <stdint.h>

// gcnlayer2: out1 = A1 @ x1 ; out2 = A2 @ x2
// R11 = R10 (proven: zero_cnt kernel + vectorized bucket + warp-per-row spmm,
//       NO counter writes inside spmm — confirmed toxic in R9) with ONE change:
//       spmm inner loop is tail-split. Full 4-edge batches run with NO per-edge
//       masking (removes ~16 ISETP/SEL per iteration from the hot path); the
//       <=3 remaining edges run in a short masked tail.

#define DFEAT 64
#define F2_PER_ROW (DFEAT / 2)    // 32 float2 per feature row
#define NN 65536                  // n_nodes
#define CAP 64                    // slots per row (deg ~ Poisson(16))

// Device-global scratch.
__device__ int  g_cnt[2][NN];
__device__ int2 g_slot[2][(size_t)NN * CAP];   // (col, val_bits)

// -------------------------------------------------------------- kernels ----

__global__ void zero_cnt_kernel(int n4) {
    int i = blockIdx.x * blockDim.x + threadIdx.x;
    if (i < n4) {
        ((int4*)g_cnt[0])[i] = make_int4(0, 0, 0, 0);
        ((int4*)g_cnt[1])[i] = make_int4(0, 0, 0, 0);
    }
}

// Bucket edges by row: 4 edges per thread, vectorized metadata loads,
// 4 independent ATOMGs in flight. (Confirmed good: 16us.)
__global__ void __launch_bounds__(256) bucket_kernel(
    const int4*   __restrict__ r1, const int4* __restrict__ c1,
    const float4* __restrict__ v1,
    const int4*   __restrict__ r2, const int4* __restrict__ c2,
    const float4* __restrict__ v2,
    int n_groups)    // n_edges / 4 per matrix
{
    int t = blockIdx.x * blockDim.x + threadIdx.x;
    if (t >= 2 * n_groups) return;
    int m = t < n_groups ? 0 : 1;
    int g = m ? t - n_groups : t;

    int4   r = __ldg(m ? &r2[g] : &r1[g]);
    int4   c = __ldg(m ? &c2[g] : &c1[g]);
    float4 v = __ldg(m ? &v2[g] : &v1[g]);

    int p0 = atomicAdd(&g_cnt[m][r.x], 1);
    int p1 = atomicAdd(&g_cnt[m][r.y], 1);
    int p2 = atomicAdd(&g_cnt[m][r.z], 1);
    int p3 = atomicAdd(&g_cnt[m][r.w], 1);

    if (p0 < CAP) g_slot[m][(size_t)r.x * CAP + p0] = make_int2(c.x, __float_as_int(v.x));
    if (p1 < CAP) g_slot[m][(size_t)r.y * CAP + p1] = make_int2(c.y, __float_as_int(v.y));
    if (p2 < CAP) g_slot[m][(size_t)r.z * CAP + p2] = make_int2(c.z, __float_as_int(v.z));
    if (p3 < CAP) g_slot[m][(size_t)r.w * CAP + p3] = make_int2(c.w, __float_as_int(v.w));
}

// Warp-per-row gather SpMM. lane owns one float2 of the 256B feature row.
// Full 4-edge batches (unmasked) + short masked tail. No writes to g_cnt.
__global__ void __launch_bounds__(256) spmm_kernel(
    const float2* __restrict__ x1,
    const float2* __restrict__ x2,
    float* __restrict__ out1,
    float* __restrict__ out2,
    int n_nodes)
{
    int warp = (blockIdx.x * blockDim.x + threadIdx.x) >> 5;
    int lane = threadIdx.x & 31;
    if (warp >= 2 * n_nodes) return;

    int m = warp < n_nodes ? 0 : 1;
    int r = m ? warp - n_nodes : warp;
    const float2* x  = m ? x2 : x1;
    float* out       = m ? out2 : out1;

    int n = g_cnt[m][r];
    if (n > CAP) n = CAP;

    const int4* ep = (const int4*)&g_slot[m][(size_t)r * CAP];  // 2 edges / int4

    float2 acc = make_float2(0.f, 0.f);
    int iters = n >> 2;           // full 4-edge batches, no masking
    int tail  = n & 3;

    if (iters > 0) {
        int4 e01 = __ldg(ep + 0);
        int4 e23 = __ldg(ep + 1);
        for (int it = 0; it < iters; it++) {
            int4 n01, n23;
            if (it + 1 < iters) {           // prefetch next batch
                n01 = __ldg(ep + 2 * it + 2);
                n23 = __ldg(ep + 2 * it + 3);
            }
            float v0 = __int_as_float(e01.y);
            float v1 = __int_as_float(e01.w);
            float v2 = __int_as_float(e23.y);
            float v3 = __int_as_float(e23.w);

            // 4 independent coalesced gathers (warp = 256B per edge row).
            float2 xa = __ldg(&x[(size_t)e01.x * F2_PER_ROW + lane]);
            float2 xb = __ldg(&x[(size_t)e01.z * F2_PER_ROW + lane]);
            float2 xc = __ldg(&x[(size_t)e23.x * F2_PER_ROW + lane]);
            float2 xd = __ldg(&x[(size_t)e23.z * F2_PER_ROW + lane]);

            acc.x += v0 * xa.x + v1 * xb.x + v2 * xc.x + v3 * xd.x;
            acc.y += v0 * xa.y + v1 * xb.y + v2 * xc.y + v3 * xd.y;

            e01 = n01;
            e23 = n23;
        }
    }

    // Masked tail: up to 3 edges.
    if (tail) {
        const int2* es = (const int2*)ep + (n & ~3);
        int2 t0 = __ldg(es + 0);
        int2 t1 = (tail > 1) ? __ldg(es + 1) : make_int2(0, 0);
        int2 t2 = (tail > 2) ? __ldg(es + 2) : make_int2(0, 0);
        float2 xa = __ldg(&x[(size_t)t0.x * F2_PER_ROW + lane]);
        float2 xb = __ldg(&x[(size_t)t1.x * F2_PER_ROW + lane]);
        float2 xc = __ldg(&x[(size_t)t2.x * F2_PER_ROW + lane]);
        float v0 = __int_as_float(t0.y);
        float v1 = __int_as_float(t1.y);
        float v2 = __int_as_float(t2.y);
        acc.x += v0 * xa.x + v1 * xb.x + v2 * xc.x;
        acc.y += v0 * xa.y + v1 * xb.y + v2 * xc.y;
    }

    // Single vector store; every row written -> no output zeroing needed.
    ((float2*)(out + (size_t)r * DFEAT))[lane] = acc;
}

// --------------------------------------------------------------- launch ----

extern "C" void kernel_launch(void* const* d_in, const int* in_sizes, int n_in,
                              void* d_out, int out_size) {
    const float* x1      = (const float*)d_in[0];
    const float* x2      = (const float*)d_in[1];
    const int*   a1_rows = (const int*)d_in[2];
    const int*   a1_cols = (const int*)d_in[3];
    const float* a1_vals = (const float*)d_in[4];
    const int*   a2_rows = (const int*)d_in[5];
    const int*   a2_cols = (const int*)d_in[6];
    const float* a2_vals = (const float*)d_in[7];

    float* out  = (float*)d_out;
    int n_edges = in_sizes[2];               // 1048576
    int n_nodes = in_sizes[0] / DFEAT;       // 65536
    int half    = n_nodes * DFEAT;
    int n_groups = n_edges / 4;

    // 1) zero per-row counters (vectorized)
    {
        int n4 = n_nodes / 4;
        zero_cnt_kernel<<<(n4 + 255) / 256, 256>>>(n4);
    }

    // 2) bucket edges by row (both matrices, one pass)
    {
        int total = 2 * n_groups;
        bucket_kernel<<<(total + 255) / 256, 256>>>(
            (const int4*)a1_rows, (const int4*)a1_cols, (const float4*)a1_vals,
            (const int4*)a2_rows, (const int4*)a2_cols, (const float4*)a2_vals,
            n_groups);
    }

    // 3) warp-per-row gather SpMM
    {
        long long total_threads = 2LL * n_nodes * 32;
        int threads = 256;
        long long blocks = (total_threads + threads - 1) / threads;
        spmm_kernel<<<(unsigned)blocks, threads>>>(
            (const float2*)x1, (const float2*)x2, out, out + half, n_nodes);
    }
}